// round 17
// baseline (speedup 1.0000x reference)
#include <cuda_runtime.h>
#include <stdint.h>

// Instant-NGP hash-grid interpolation encoding.
// B=262144 points, DIM=3, L=16 levels, T=19 (2^19-entry tables), F=2 features.
//
// Final kernel (R3 structure, 78.3us). Thread = (point, level).
// PRIMES[0]==1: even g0 collapses the two x-corners of every (dim1,dim2)
// combo into one aligned float4 load (4 loads); odd g0 -> 8 float2 gathers.
// Avg 6 lane-loads/thread. L1tex gather-wavefront bound (~88% of peak),
// co-bound with L2 sector traffic (~72%).
//
// Verified dead ends: .cg bypass (R4), 256-bit loads (R5), predicated
// unification (R6: regs), spatial sort (R8: aux cost > locality win),
// dense remapped tables (R9: divergence, no lane merging), shuffle x-loads /
// streaming stores (R11: broadcast loads already ~free). Sorted level-major
// warps price net-negative analytically (sort ~23us + store scatter ~13us
// vs ~13us gather-wavefront saving).
//
// This revision only reorders: gather LDGs are issued before the weight
// products are computed, shortening the path to first load issue.

#define NB   262144
#define NL   16
#define TBITS 19
#define TMASK ((1u << TBITS) - 1u)

__constant__ float c_res[NL] = {
    16.f, 20.f, 25.f, 32.f, 40.f, 50.f, 64.f, 80.f,
    101.f, 128.f, 161.f, 203.f, 256.f, 322.f, 406.f, 512.f
};

__global__ void __launch_bounds__(256)
ngp_interp_kernel(const float* __restrict__ x,
                  const float2* __restrict__ tables,
                  float2* __restrict__ out)
{
    const int tid = blockIdx.x * 256 + threadIdx.x;   // tid = b*16 + l
    const int l = tid & (NL - 1);
    const int b = tid >> 4;

    const float res = c_res[l];

    // 16 lanes share the same point -> broadcast-coalesced, ~free.
    const float x0 = __ldg(x + b * 3 + 0);
    const float x1 = __ldg(x + b * 3 + 1);
    const float x2 = __ldg(x + b * 3 + 2);

    const float s0 = x0 * res, s1 = x1 * res, s2 = x2 * res;
    const float g0f = floorf(s0), g1f = floorf(s1), g2f = floorf(s2);

    const unsigned g0 = (unsigned)g0f;
    const unsigned g1 = (unsigned)g1f;
    const unsigned g2 = (unsigned)g2f;

    const unsigned P1 = 2654435761u, P2 = 805459861u;

    const unsigned h1a = g1 * P1, h1b = (g1 + 1u) * P1;
    const unsigned h2a = g2 * P2, h2b = (g2 + 1u) * P2;

    const float2* __restrict__ tab = tables + ((size_t)l << TBITS);

    // Index math only before the loads; weight math deferred until after
    // the LDGs are in flight.
    unsigned hy[4];
    hy[0] = h1a ^ h2a;  hy[1] = h1b ^ h2a;
    hy[2] = h1a ^ h2b;  hy[3] = h1b ^ h2b;

    float a0 = 0.f, a1 = 0.f;

    if ((g0 & 1u) == 0u) {
        // g0 even: x-corner pair = {idx, idx^1} -> aligned float4.
        const float4* __restrict__ tab4 = (const float4*)tab;

        unsigned idxA[4];
#pragma unroll
        for (int p = 0; p < 4; p++) idxA[p] = (g0 ^ hy[p]) & TMASK;

        float4 q[4];
#pragma unroll
        for (int p = 0; p < 4; p++) q[p] = __ldg(tab4 + (idxA[p] >> 1));

        // Weights computed while loads are in flight.
        const float f0 = s0 - g0f, f1 = s1 - g1f, f2 = s2 - g2f;
        const float w0a = 1.f - f0, w0b = f0;
        const float w1a = 1.f - f1, w1b = f1;
        const float w2a = 1.f - f2, w2b = f2;
        float wp[4];
        wp[0] = w1a * w2a;  wp[1] = w1b * w2a;
        wp[2] = w1a * w2b;  wp[3] = w1b * w2b;

#pragma unroll
        for (int p = 0; p < 4; p++) {
            const bool hi = (idxA[p] & 1u) != 0u;
            // corner A = border0 (weight w0a) lives at idxA; B at idxA^1.
            const float vax = hi ? q[p].z : q[p].x;
            const float vay = hi ? q[p].w : q[p].y;
            const float vbx = hi ? q[p].x : q[p].z;
            const float vby = hi ? q[p].y : q[p].w;
            const float wA = w0a * wp[p];
            const float wB = w0b * wp[p];
            a0 += wA * vax + wB * vbx;
            a1 += wA * vay + wB * vby;
        }
    } else {
        // g0 odd: corners not adjacent -> 8 independent float2 gathers.
        const unsigned h0a = g0, h0b = g0 + 1u;

        unsigned idx[8];
#pragma unroll
        for (int p = 0; p < 4; p++) {
            idx[2 * p + 0] = (h0a ^ hy[p]) & TMASK;
            idx[2 * p + 1] = (h0b ^ hy[p]) & TMASK;
        }

        float2 v[8];
#pragma unroll
        for (int i = 0; i < 8; i++) v[i] = __ldg(tab + idx[i]);

        // Weights computed while loads are in flight.
        const float f0 = s0 - g0f, f1 = s1 - g1f, f2 = s2 - g2f;
        const float w0a = 1.f - f0, w0b = f0;
        const float w1a = 1.f - f1, w1b = f1;
        const float w2a = 1.f - f2, w2b = f2;
        float wp[4];
        wp[0] = w1a * w2a;  wp[1] = w1b * w2a;
        wp[2] = w1a * w2b;  wp[3] = w1b * w2b;

#pragma unroll
        for (int p = 0; p < 4; p++) {
            const float wA = w0a * wp[p];
            const float wB = w0b * wp[p];
            a0 += wA * v[2 * p].x + wB * v[2 * p + 1].x;
            a1 += wA * v[2 * p].y + wB * v[2 * p + 1].y;
        }
    }

    out[tid] = make_float2(a0, a1);   // out[b,l]: fully coalesced
}

extern "C" void kernel_launch(void* const* d_in, const int* in_sizes, int n_in,
                              void* d_out, int out_size)
{
    // Robust input-order detection: x has 262144*3 = 786432 elements,
    // tables has 16*2^19*2 = 16777216 elements.
    const float* x   = (const float*)d_in[0];
    const float* tab = (const float*)d_in[1];
    if (n_in >= 2 && in_sizes[0] > in_sizes[1]) {
        const float* t = x; x = tab; tab = t;
    }

    const int total = NB * NL;
    ngp_interp_kernel<<<total / 256, 256>>>(x, (const float2*)tab, (float2*)d_out);
}